// round 7
// baseline (speedup 1.0000x reference)
#include <cuda_runtime.h>
#include <cuda_bf16.h>
#include <cstdint>

#define D   4096
#define BSR 4096
#define SEQ 1024
#define NH  32
#define HD  128
#define LR  16

// ------------------------- device scratch ---------------------------------
__device__ __nv_bfloat16 g_xh[(size_t)BSR * D], g_xl[(size_t)BSR * D];
__device__ __nv_bfloat16 g_Wqh[(size_t)D * D], g_Wql[(size_t)D * D];
__device__ __nv_bfloat16 g_Wkh[(size_t)D * D], g_Wkl[(size_t)D * D];
__device__ __nv_bfloat16 g_Wvh[(size_t)D * D], g_Wvl[(size_t)D * D];
__device__ __nv_bfloat16 g_Woh[(size_t)D * D], g_Wol[(size_t)D * D];
__device__ __nv_bfloat16 g_Oh[(size_t)BSR * D], g_Ol[(size_t)BSR * D];
__device__ float g_Q[(size_t)BSR * D], g_K[(size_t)BSR * D];
__device__ float g_V[(size_t)BSR * D];

// ------------------------- PTX helpers (base-target only) ------------------
__device__ __forceinline__ uint32_t smem_to_u32(const void* p) {
    uint32_t a;
    asm("{ .reg .u64 t; cvta.to.shared.u64 t, %1; cvt.u32.u64 %0, t; }"
        : "=r"(a) : "l"(p));
    return a;
}
#define CP16(dst, src) \
    asm volatile("cp.async.cg.shared.global [%0], [%1], 16;" \
                 :: "r"(dst), "l"(src))
#define CP_COMMIT() asm volatile("cp.async.commit_group;" ::: "memory")
#define CP_WAIT1()  asm volatile("cp.async.wait_group 1;" ::: "memory")
#define CP_WAIT0()  asm volatile("cp.async.wait_group 0;" ::: "memory")

#define LDSM4(r0, r1, r2, r3, addr) \
    asm volatile("ldmatrix.sync.aligned.m8n8.x4.shared.b16 {%0,%1,%2,%3}, [%4];" \
                 : "=r"(r0), "=r"(r1), "=r"(r2), "=r"(r3) : "r"(addr))
#define LDSM2(r0, r1, addr) \
    asm volatile("ldmatrix.sync.aligned.m8n8.x2.shared.b16 {%0,%1}, [%2];" \
                 : "=r"(r0), "=r"(r1) : "r"(addr))
#define MMA16816(c, a0, a1, a2, a3, b0, b1) \
    asm volatile("mma.sync.aligned.m16n8k16.row.col.f32.bf16.bf16.f32 " \
                 "{%0,%1,%2,%3}, {%4,%5,%6,%7}, {%8,%9}, {%0,%1,%2,%3};" \
                 : "+f"((c)[0]), "+f"((c)[1]), "+f"((c)[2]), "+f"((c)[3]) \
                 : "r"(a0), "r"(a1), "r"(a2), "r"(a3), "r"(b0), "r"(b1))

// ------------------------- split / merge kernels --------------------------
__global__ void split8(const float* __restrict__ in,
                       __nv_bfloat16* __restrict__ hi,
                       __nv_bfloat16* __restrict__ lo) {
    size_t i = ((size_t)blockIdx.x * 256 + threadIdx.x) * 8;
    float v[8];
    *(float4*)&v[0] = *(const float4*)(in + i);
    *(float4*)&v[4] = *(const float4*)(in + i + 4);
    __nv_bfloat16 h[8], l[8];
#pragma unroll
    for (int j = 0; j < 8; j++) {
        h[j] = __float2bfloat16(v[j]);
        l[j] = __float2bfloat16(v[j] - __bfloat162float(h[j]));
    }
    *(float4*)(hi + i) = *(float4*)h;
    *(float4*)(lo + i) = *(float4*)l;
}

__global__ void merge_split(const float* __restrict__ w,
                            const float* __restrict__ a,
                            const float* __restrict__ b,
                            __nv_bfloat16* __restrict__ hi,
                            __nv_bfloat16* __restrict__ lo) {
    int idx = blockIdx.x * 256 + threadIdx.x;
    int n = idx >> 12, k = idx & (D - 1);
    float acc = w[idx];
#pragma unroll
    for (int r = 0; r < LR; r++)
        acc += 2.0f * __ldg(&b[n * LR + r]) * __ldg(&a[r * D + k]);
    __nv_bfloat16 h = __float2bfloat16(acc);
    hi[idx] = h;
    lo[idx] = __float2bfloat16(acc - __bfloat162float(h));
}

// ------------- bf16-split GEMM (NT) on mma.sync tensor cores --------------
// C = Ah*Bh^T + Ah*Bl^T + Al*Bh^T.  BM=256, BN=128, BK=64.
// 256 threads (8 warps, 4M x 2N grid, warp tile 64x64).
// SMEM stage: Ah 32K | Al 32K | Bh 16K | Bl 16K = 96K; 2 stages = 192K.
// MODE: 0 = plain store, 1 = fused RoPE store (C is Q or K).
#define GSTAGE  98304
#define GEMM_SMEM (2 * GSTAGE)
#define NCHUNK  64   // D / BK = 4096 / 64 (R5/R6 bug: was 32 -> only half of K)

template <int MODE>
__global__ void __launch_bounds__(256, 1) gemm_mma3(
    const __nv_bfloat16* __restrict__ Ah, const __nv_bfloat16* __restrict__ Al,
    const __nv_bfloat16* __restrict__ Bh, const __nv_bfloat16* __restrict__ Bl,
    float* __restrict__ C,
    const float* __restrict__ fc, const float* __restrict__ fs) {
    extern __shared__ char smch[];
    const uint32_t smb = smem_to_u32(smch);
    const int tid = threadIdx.x, lane = tid & 31, wid = tid >> 5;
    const int warp_m = wid & 3;          // 4 x 64 rows
    const int warp_n = wid >> 2;         // 2 x 64 cols
    const int bm = blockIdx.y * 256, bn = blockIdx.x * 128;

    float acc[4][8][4];
#pragma unroll
    for (int i = 0; i < 4; i++)
#pragma unroll
        for (int j = 0; j < 8; j++)
#pragma unroll
            for (int k = 0; k < 4; k++) acc[i][j][k] = 0.0f;

    // loader mapping: row0 = tid/8 (0..31), 16B chunk c0 = tid%8
    const int r0 = tid >> 3, c0 = tid & 7;
    const uint32_t sx = (uint32_t)((c0 ^ (r0 & 7)) * 16);
    const __nv_bfloat16* gAh = Ah + ((size_t)(bm + r0) << 12) + c0 * 8;
    const __nv_bfloat16* gAl = Al + ((size_t)(bm + r0) << 12) + c0 * 8;
    const __nv_bfloat16* gBh = Bh + ((size_t)(bn + r0) << 12) + c0 * 8;
    const __nv_bfloat16* gBl = Bl + ((size_t)(bn + r0) << 12) + c0 * 8;

#define ISSUE(ck, st) do {                                                     \
        const uint32_t sb_ = smb + (st) * GSTAGE;                              \
        const size_t go_ = (size_t)(ck) * 64;                                  \
        _Pragma("unroll")                                                      \
        for (int j = 0; j < 8; j++) {                                          \
            const uint32_t d_ = sb_ + (uint32_t)((r0 + j * 32) * 128) + sx;    \
            const size_t s_ = go_ + ((size_t)j << 17);                         \
            CP16(d_,         (const char*)(gAh + s_));                         \
            CP16(d_ + 32768, (const char*)(gAl + s_));                         \
        }                                                                      \
        _Pragma("unroll")                                                      \
        for (int j = 0; j < 4; j++) {                                          \
            const uint32_t d_ = sb_ + 65536 + (uint32_t)((r0 + j * 32) * 128) + sx; \
            const size_t s_ = go_ + ((size_t)j << 17);                         \
            CP16(d_,         (const char*)(gBh + s_));                         \
            CP16(d_ + 16384, (const char*)(gBl + s_));                         \
        }                                                                      \
        CP_COMMIT();                                                           \
    } while (0)

    ISSUE(0, 0);
    ISSUE(1, 1);

    const int arow = warp_m * 64 + (lane & 15);
    const int akh  = lane >> 4;
    const int brow = warp_n * 64 + (lane & 7);
    const int bkh  = (lane >> 3) & 1;

    for (int ck = 0; ck < NCHUNK; ck++) {
        const int st = ck & 1;
        // Tail: once no further groups will be issued, wait_group 1 no longer
        // guarantees the current stage's group — drain fully instead.
        if (ck + 2 >= NCHUNK) { CP_WAIT0(); } else { CP_WAIT1(); }
        __syncthreads();

        const uint32_t sAh = smb + st * GSTAGE;
        const uint32_t sAl = sAh + 32768;
        const uint32_t sBh = sAh + 65536;
        const uint32_t sBl = sAh + 81920;

#pragma unroll
        for (int ks = 0; ks < 4; ks++) {
            uint32_t bh[8][2], bl[8][2];
#pragma unroll
            for (int nt = 0; nt < 8; nt++) {
                const int r = brow + nt * 8;
                const uint32_t adr = r * 128 + (((ks * 2 + bkh) ^ (r & 7)) * 16);
                LDSM2(bh[nt][0], bh[nt][1], sBh + adr);
                LDSM2(bl[nt][0], bl[nt][1], sBl + adr);
            }
#pragma unroll
            for (int mt = 0; mt < 4; mt++) {
                const int r = arow + mt * 16;
                const uint32_t adr = r * 128 + (((ks * 2 + akh) ^ (r & 7)) * 16);
                uint32_t ah[4], al[4];
                LDSM4(ah[0], ah[1], ah[2], ah[3], sAh + adr);
                LDSM4(al[0], al[1], al[2], al[3], sAl + adr);
#pragma unroll
                for (int nt = 0; nt < 8; nt++) {
                    MMA16816(acc[mt][nt], ah[0], ah[1], ah[2], ah[3],
                             bh[nt][0], bh[nt][1]);
                    MMA16816(acc[mt][nt], ah[0], ah[1], ah[2], ah[3],
                             bl[nt][0], bl[nt][1]);
                    MMA16816(acc[mt][nt], al[0], al[1], al[2], al[3],
                             bh[nt][0], bh[nt][1]);
                }
            }
        }
        __syncthreads();
        if (ck + 2 < NCHUNK) ISSUE(ck + 2, st);
    }

    // epilogue (optionally fused RoPE for Q/K)
#pragma unroll
    for (int mt = 0; mt < 4; mt++) {
        const int row = bm + warp_m * 64 + mt * 16 + (lane >> 2);
#pragma unroll
        for (int nt = 0; nt < 8; nt++) {
            const int col = bn + warp_n * 64 + nt * 8 + (lane & 3) * 2;
            float v0 = acc[mt][nt][0], v1 = acc[mt][nt][1];
            float v2 = acc[mt][nt][2], v3 = acc[mt][nt][3];
            if (MODE == 1) {
                const int i = (col & (HD - 1)) >> 1;
                const int s1 = row & (SEQ - 1);
                const int s2 = (row + 8) & (SEQ - 1);
                const float c1 = __ldg(&fc[s1 * 64 + i]), n1 = __ldg(&fs[s1 * 64 + i]);
                const float c2 = __ldg(&fc[s2 * 64 + i]), n2 = __ldg(&fs[s2 * 64 + i]);
                float t;
                t  = v0 * c1 - v1 * n1; v1 = v0 * n1 + v1 * c1; v0 = t;
                t  = v2 * c2 - v3 * n2; v3 = v2 * n2 + v3 * c2; v2 = t;
            }
            *(float2*)&C[(size_t)row * D + col]       = make_float2(v0, v1);
            *(float2*)&C[(size_t)(row + 8) * D + col] = make_float2(v2, v3);
        }
    }
}

// ---------------- flash attention (fp32, causal) ---------------------------
// epilogue writes bf16 hi/lo directly (feeds O-projection GEMM).
#define ATTN_SMEM ((128 * 132 + 64 * 132 + 64 * 132 + 128 * 68) * 4)

__global__ void __launch_bounds__(256) attn_kernel() {
    extern __shared__ float smf[];
    float* Qs = smf;
    float* Ks = smf + 128 * 132;
    float* Vs = Ks + 64 * 132;
    float* Ps = Vs + 64 * 132;

    const int b = blockIdx.z, h = blockIdx.y, qt = blockIdx.x;
    const int q0 = qt * 128;
    const int tid = threadIdx.x;
    const int tx = tid & 7, ty = tid >> 3;
    const float SCALE = 0.08838834764831845f;

    const float* Qg = g_Q + ((size_t)(b * SEQ + q0)) * D + h * HD;
    const float* Kg = g_K + ((size_t)(b * SEQ)) * D + h * HD;
    const float* Vg = g_V + ((size_t)(b * SEQ)) * D + h * HD;

    for (int l = tid; l < 128 * 32; l += 256) {
        int row = l >> 5, c4 = l & 31;
        *(float4*)&Qs[row * 132 + c4 * 4] = *(const float4*)&Qg[(size_t)row * D + c4 * 4];
    }

    float o[4][16];
    float m[4], lsum[4];
#pragma unroll
    for (int r = 0; r < 4; r++) {
        m[r] = -1e30f; lsum[r] = 0.0f;
#pragma unroll
        for (int c = 0; c < 16; c++) o[r][c] = 0.0f;
    }

    const int ktiles = 2 * qt + 2;
    for (int kt = 0; kt < ktiles; kt++) {
        const int k0 = kt * 64;
        __syncthreads();
        for (int l = tid; l < 64 * 32; l += 256) {
            int row = l >> 5, c4 = l & 31;
            *(float4*)&Ks[row * 132 + c4 * 4] = *(const float4*)&Kg[(size_t)(k0 + row) * D + c4 * 4];
            *(float4*)&Vs[row * 132 + c4 * 4] = *(const float4*)&Vg[(size_t)(k0 + row) * D + c4 * 4];
        }
        __syncthreads();

        float sc[4][8];
#pragma unroll
        for (int r = 0; r < 4; r++)
#pragma unroll
            for (int c = 0; c < 8; c++) sc[r][c] = 0.0f;

#pragma unroll 4
        for (int kk4 = 0; kk4 < 32; kk4++) {
            float4 a4[4], b4[8];
#pragma unroll
            for (int r = 0; r < 4; r++)
                a4[r] = *(const float4*)&Qs[(ty * 4 + r) * 132 + kk4 * 4];
#pragma unroll
            for (int c = 0; c < 8; c++)
                b4[c] = *(const float4*)&Ks[(tx + 8 * c) * 132 + kk4 * 4];
#pragma unroll
            for (int r = 0; r < 4; r++)
#pragma unroll
                for (int c = 0; c < 8; c++)
                    sc[r][c] += a4[r].x * b4[c].x + a4[r].y * b4[c].y +
                                a4[r].z * b4[c].z + a4[r].w * b4[c].w;
        }

        const bool need_mask = (k0 + 63 > q0);
#pragma unroll
        for (int r = 0; r < 4; r++) {
            int ig = q0 + ty * 4 + r;
#pragma unroll
            for (int c = 0; c < 8; c++) {
                float v = sc[r][c] * SCALE;
                if (need_mask && (k0 + tx + 8 * c > ig)) v = -1e30f;
                sc[r][c] = v;
            }
        }

#pragma unroll
        for (int r = 0; r < 4; r++) {
            float mx = sc[r][0];
#pragma unroll
            for (int c = 1; c < 8; c++) mx = fmaxf(mx, sc[r][c]);
            mx = fmaxf(mx, __shfl_xor_sync(0xffffffffu, mx, 1));
            mx = fmaxf(mx, __shfl_xor_sync(0xffffffffu, mx, 2));
            mx = fmaxf(mx, __shfl_xor_sync(0xffffffffu, mx, 4));
            float mnew = fmaxf(m[r], mx);
            float alpha = __expf(m[r] - mnew);
            float s = 0.0f;
#pragma unroll
            for (int c = 0; c < 8; c++) {
                float p = __expf(sc[r][c] - mnew);
                sc[r][c] = p;
                s += p;
            }
            s += __shfl_xor_sync(0xffffffffu, s, 1);
            s += __shfl_xor_sync(0xffffffffu, s, 2);
            s += __shfl_xor_sync(0xffffffffu, s, 4);
            lsum[r] = lsum[r] * alpha + s;
            m[r] = mnew;
#pragma unroll
            for (int c = 0; c < 16; c++) o[r][c] *= alpha;
        }

#pragma unroll
        for (int r = 0; r < 4; r++)
#pragma unroll
            for (int c = 0; c < 8; c++)
                Ps[(ty * 4 + r) * 68 + tx + 8 * c] = sc[r][c];
        __syncthreads();

#pragma unroll 2
        for (int j = 0; j < 64; j++) {
            float p[4];
#pragma unroll
            for (int r = 0; r < 4; r++) p[r] = Ps[(ty * 4 + r) * 68 + j];
#pragma unroll
            for (int c = 0; c < 16; c++) {
                float v = Vs[j * 132 + tx + 8 * c];
#pragma unroll
                for (int r = 0; r < 4; r++) o[r][c] += p[r] * v;
            }
        }
    }

    // epilogue: normalize + split to bf16 hi/lo directly
#pragma unroll
    for (int r = 0; r < 4; r++) {
        float inv = 1.0f / lsum[r];
        size_t rowoff = ((size_t)(b * SEQ + q0 + ty * 4 + r)) * D + h * HD;
#pragma unroll
        for (int c = 0; c < 16; c++) {
            float val = o[r][c] * inv;
            __nv_bfloat16 hh = __float2bfloat16(val);
            g_Oh[rowoff + tx + 8 * c] = hh;
            g_Ol[rowoff + tx + 8 * c] = __float2bfloat16(val - __bfloat162float(hh));
        }
    }
}

// ---------------- launcher -------------------------------------------------
extern "C" void kernel_launch(void* const* d_in, const int* in_sizes, int n_in,
                              void* d_out, int out_size) {
    const float* x    = (const float*)d_in[0];
    const float* wq_w = (const float*)d_in[1];
    const float* wq_a = (const float*)d_in[2];
    const float* wq_b = (const float*)d_in[3];
    const float* wk_w = (const float*)d_in[4];
    const float* wv_w = (const float*)d_in[5];
    const float* wv_a = (const float*)d_in[6];
    const float* wv_b = (const float*)d_in[7];
    const float* wo_w = (const float*)d_in[8];
    const float* fc   = (const float*)d_in[9];
    const float* fs   = (const float*)d_in[10];
    float* out = (float*)d_out;

    __nv_bfloat16 *xh, *xl, *Wqh, *Wql, *Wkh, *Wkl, *Wvh, *Wvl, *Woh, *Wol, *Oh, *Ol;
    float *Q, *K, *V;
    cudaGetSymbolAddress((void**)&xh, g_xh);   cudaGetSymbolAddress((void**)&xl, g_xl);
    cudaGetSymbolAddress((void**)&Wqh, g_Wqh); cudaGetSymbolAddress((void**)&Wql, g_Wql);
    cudaGetSymbolAddress((void**)&Wkh, g_Wkh); cudaGetSymbolAddress((void**)&Wkl, g_Wkl);
    cudaGetSymbolAddress((void**)&Wvh, g_Wvh); cudaGetSymbolAddress((void**)&Wvl, g_Wvl);
    cudaGetSymbolAddress((void**)&Woh, g_Woh); cudaGetSymbolAddress((void**)&Wol, g_Wol);
    cudaGetSymbolAddress((void**)&Oh, g_Oh);   cudaGetSymbolAddress((void**)&Ol, g_Ol);
    cudaGetSymbolAddress((void**)&Q, g_Q);     cudaGetSymbolAddress((void**)&K, g_K);
    cudaGetSymbolAddress((void**)&V, g_V);

    cudaFuncSetAttribute(gemm_mma3<0>,
                         cudaFuncAttributeMaxDynamicSharedMemorySize, GEMM_SMEM);
    cudaFuncSetAttribute(gemm_mma3<1>,
                         cudaFuncAttributeMaxDynamicSharedMemorySize, GEMM_SMEM);
    cudaFuncSetAttribute(attn_kernel,
                         cudaFuncAttributeMaxDynamicSharedMemorySize, ATTN_SMEM);

    // 1) fold LoRA + split to bf16 hi/lo
    merge_split<<<(D * D) / 256, 256>>>(wq_w, wq_a, wq_b, Wqh, Wql);
    merge_split<<<(D * D) / 256, 256>>>(wv_w, wv_a, wv_b, Wvh, Wvl);
    split8<<<(D * D) / 8 / 256, 256>>>(wk_w, Wkh, Wkl);
    split8<<<(D * D) / 8 / 256, 256>>>(wo_w, Woh, Wol);
    split8<<<((size_t)BSR * D) / 8 / 256, 256>>>(x, xh, xl);

    // 2) projections on tensor cores; RoPE fused into Q/K epilogues
    dim3 g(D / 128, BSR / 256);  // (32, 16)
    gemm_mma3<1><<<g, 256, GEMM_SMEM>>>(xh, xl, Wqh, Wql, Q, fc, fs);
    gemm_mma3<1><<<g, 256, GEMM_SMEM>>>(xh, xl, Wkh, Wkl, K, fc, fs);
    gemm_mma3<0><<<g, 256, GEMM_SMEM>>>(xh, xl, Wvh, Wvl, V, fc, fs);

    // 3) causal flash attention -> g_Oh/g_Ol (bf16 split fused in epilogue)
    attn_kernel<<<dim3(SEQ / 128, NH, 4), 256, ATTN_SMEM>>>();

    // 4) output projection
    gemm_mma3<0><<<g, 256, GEMM_SMEM>>>(Oh, Ol, Woh, Wol, out, fc, fs);
}

// round 8
// speedup vs baseline: 1.6342x; 1.6342x over previous
#include <cuda_runtime.h>
#include <cuda_bf16.h>
#include <cstdint>

#define D   4096
#define BSR 4096
#define SEQ 1024
#define NH  32
#define HD  128
#define LR  16

// ------------------------- device scratch ---------------------------------
__device__ __nv_bfloat16 g_xh[(size_t)BSR * D], g_xl[(size_t)BSR * D];
__device__ __nv_bfloat16 g_Wqh[(size_t)D * D], g_Wql[(size_t)D * D];
__device__ __nv_bfloat16 g_Wkh[(size_t)D * D], g_Wkl[(size_t)D * D];
__device__ __nv_bfloat16 g_Wvh[(size_t)D * D], g_Wvl[(size_t)D * D];
__device__ __nv_bfloat16 g_Woh[(size_t)D * D], g_Wol[(size_t)D * D];
__device__ __nv_bfloat16 g_Oh[(size_t)BSR * D], g_Ol[(size_t)BSR * D];
__device__ float g_Q[(size_t)BSR * D], g_K[(size_t)BSR * D];
__device__ float g_V[(size_t)BSR * D];

// ------------------------- PTX helpers (base-target only) ------------------
__device__ __forceinline__ uint32_t smem_to_u32(const void* p) {
    uint32_t a;
    asm("{ .reg .u64 t; cvta.to.shared.u64 t, %1; cvt.u32.u64 %0, t; }"
        : "=r"(a) : "l"(p));
    return a;
}
#define CP16(dst, src) \
    asm volatile("cp.async.cg.shared.global [%0], [%1], 16;" \
                 :: "r"(dst), "l"(src))
#define CP_COMMIT() asm volatile("cp.async.commit_group;" ::: "memory")
#define CP_WAIT1()  asm volatile("cp.async.wait_group 1;" ::: "memory")
#define CP_WAIT0()  asm volatile("cp.async.wait_group 0;" ::: "memory")

#define LDSM4(r0, r1, r2, r3, addr) \
    asm volatile("ldmatrix.sync.aligned.m8n8.x4.shared.b16 {%0,%1,%2,%3}, [%4];" \
                 : "=r"(r0), "=r"(r1), "=r"(r2), "=r"(r3) : "r"(addr))
#define LDSM2(r0, r1, addr) \
    asm volatile("ldmatrix.sync.aligned.m8n8.x2.shared.b16 {%0,%1}, [%2];" \
                 : "=r"(r0), "=r"(r1) : "r"(addr))
#define MMA16816(c, a0, a1, a2, a3, b0, b1) \
    asm volatile("mma.sync.aligned.m16n8k16.row.col.f32.bf16.bf16.f32 " \
                 "{%0,%1,%2,%3}, {%4,%5,%6,%7}, {%8,%9}, {%0,%1,%2,%3};" \
                 : "+f"((c)[0]), "+f"((c)[1]), "+f"((c)[2]), "+f"((c)[3]) \
                 : "r"(a0), "r"(a1), "r"(a2), "r"(a3), "r"(b0), "r"(b1))

// ------------------------- split / merge kernels --------------------------
__global__ void split8(const float* __restrict__ in,
                       __nv_bfloat16* __restrict__ hi,
                       __nv_bfloat16* __restrict__ lo) {
    size_t i = ((size_t)blockIdx.x * 256 + threadIdx.x) * 8;
    float v[8];
    *(float4*)&v[0] = *(const float4*)(in + i);
    *(float4*)&v[4] = *(const float4*)(in + i + 4);
    __nv_bfloat16 h[8], l[8];
#pragma unroll
    for (int j = 0; j < 8; j++) {
        h[j] = __float2bfloat16(v[j]);
        l[j] = __float2bfloat16(v[j] - __bfloat162float(h[j]));
    }
    *(float4*)(hi + i) = *(float4*)h;
    *(float4*)(lo + i) = *(float4*)l;
}

__global__ void merge_split(const float* __restrict__ w,
                            const float* __restrict__ a,
                            const float* __restrict__ b,
                            __nv_bfloat16* __restrict__ hi,
                            __nv_bfloat16* __restrict__ lo) {
    int idx = blockIdx.x * 256 + threadIdx.x;
    int n = idx >> 12, k = idx & (D - 1);
    float acc = w[idx];
#pragma unroll
    for (int r = 0; r < LR; r++)
        acc += 2.0f * __ldg(&b[n * LR + r]) * __ldg(&a[r * D + k]);
    __nv_bfloat16 h = __float2bfloat16(acc);
    hi[idx] = h;
    lo[idx] = __float2bfloat16(acc - __bfloat162float(h));
}

// ------------- bf16-split GEMM (NT) on mma.sync tensor cores --------------
// C = Ah*Bh^T + Ah*Bl^T + Al*Bh^T.  BM=BN=128, BK=64, 256 thr (8 warps 2x4).
// SMEM: 3 stages x 4 tiles (Ah,Al,Bh,Bl), tile = 128 rows x 128B, XOR-swizzled.
// R4-proven topology; single barrier per chunk; tail-drained pipeline.
// MODE: 0 = plain store, 1 = fused RoPE store (C is Q or K).
#define GTILE   16384
#define GSTAGE  (4 * GTILE)
#define NSTAGE  3
#define GEMM_SMEM (NSTAGE * GSTAGE)
#define NCHUNK  64   // D / BK

template <int MODE>
__global__ void __launch_bounds__(256, 1) gemm_mma3(
    const __nv_bfloat16* __restrict__ Ah, const __nv_bfloat16* __restrict__ Al,
    const __nv_bfloat16* __restrict__ Bh, const __nv_bfloat16* __restrict__ Bl,
    float* __restrict__ C,
    const float* __restrict__ fc, const float* __restrict__ fs) {
    extern __shared__ char smch[];
    const uint32_t smb = smem_to_u32(smch);
    const int tid = threadIdx.x, lane = tid & 31, wid = tid >> 5;
    const int warp_m = wid & 1;          // 64 rows each
    const int warp_n = wid >> 1;         // 32 cols each
    const int bm = blockIdx.y * 128, bn = blockIdx.x * 128;

    float acc[4][4][4];
#pragma unroll
    for (int i = 0; i < 4; i++)
#pragma unroll
        for (int j = 0; j < 4; j++)
#pragma unroll
            for (int k = 0; k < 4; k++) acc[i][j][k] = 0.0f;

    // loader mapping: thread -> (row0 = tid/8, chunk c0 = tid%8), 4 row-groups
    const int r0 = tid >> 3, c0 = tid & 7;
    const uint32_t dst0 = r0 * 128 + (uint32_t)((c0 ^ (r0 & 7)) * 16);
    const __nv_bfloat16* gAh = Ah + ((size_t)(bm + r0) << 12) + c0 * 8;
    const __nv_bfloat16* gAl = Al + ((size_t)(bm + r0) << 12) + c0 * 8;
    const __nv_bfloat16* gBh = Bh + ((size_t)(bn + r0) << 12) + c0 * 8;
    const __nv_bfloat16* gBl = Bl + ((size_t)(bn + r0) << 12) + c0 * 8;

#define ISSUE(ck, st) do {                                                     \
        const uint32_t sb_ = smb + (st) * GSTAGE + dst0;                       \
        const size_t go_ = (size_t)(ck) * 64;                                  \
        _Pragma("unroll")                                                      \
        for (int j = 0; j < 4; j++) {                                          \
            const uint32_t d_ = sb_ + j * 32 * 128;                            \
            const size_t s_ = go_ + ((size_t)j << 17);  /* 32 rows * 4096 */   \
            CP16(d_,             (const char*)(gAh + s_));                     \
            CP16(d_ + GTILE,     (const char*)(gAl + s_));                     \
            CP16(d_ + 2 * GTILE, (const char*)(gBh + s_));                     \
            CP16(d_ + 3 * GTILE, (const char*)(gBl + s_));                     \
        }                                                                      \
        CP_COMMIT();                                                           \
    } while (0)

    ISSUE(0, 0);
    ISSUE(1, 1);

    // ldmatrix per-lane bases
    const int arow = warp_m * 64 + (lane & 15);        // + mt*16
    const int akh  = lane >> 4;                         // k half
    const int brow = warp_n * 32 + (lane & 7);          // + nt*8
    const int bkh  = (lane >> 3) & 1;

    for (int ck = 0; ck < NCHUNK; ck++) {
        const int st = ck % NSTAGE;
        // Tail: once no further groups will be issued, wait_group 1 no longer
        // guarantees the current stage's group — drain fully instead.
        if (ck + 2 >= NCHUNK) { CP_WAIT0(); } else { CP_WAIT1(); }
        __syncthreads();
        // Safe to overwrite stage (ck+2)%3 == (ck-1)%3: consumed in iter ck-1,
        // and every thread passed the barrier above only after finishing it.
        if (ck + 2 < NCHUNK) ISSUE(ck + 2, (ck + 2) % NSTAGE);

        const uint32_t sAh = smb + st * GSTAGE;
        const uint32_t sAl = sAh + GTILE;
        const uint32_t sBh = sAh + 2 * GTILE;
        const uint32_t sBl = sAh + 3 * GTILE;

#pragma unroll
        for (int ks = 0; ks < 4; ks++) {
            uint32_t ah[4][4], al[4][4], bh[4][2], bl[4][2];
#pragma unroll
            for (int mt = 0; mt < 4; mt++) {
                const int r = arow + mt * 16;
                const uint32_t adr = r * 128 + (((ks * 2 + akh) ^ (r & 7)) * 16);
                LDSM4(ah[mt][0], ah[mt][1], ah[mt][2], ah[mt][3], sAh + adr);
                LDSM4(al[mt][0], al[mt][1], al[mt][2], al[mt][3], sAl + adr);
            }
#pragma unroll
            for (int nt = 0; nt < 4; nt++) {
                const int r = brow + nt * 8;
                const uint32_t adr = r * 128 + (((ks * 2 + bkh) ^ (r & 7)) * 16);
                LDSM2(bh[nt][0], bh[nt][1], sBh + adr);
                LDSM2(bl[nt][0], bl[nt][1], sBl + adr);
            }
#pragma unroll
            for (int mt = 0; mt < 4; mt++)
#pragma unroll
                for (int nt = 0; nt < 4; nt++) {
                    MMA16816(acc[mt][nt], ah[mt][0], ah[mt][1], ah[mt][2], ah[mt][3],
                             bh[nt][0], bh[nt][1]);
                    MMA16816(acc[mt][nt], ah[mt][0], ah[mt][1], ah[mt][2], ah[mt][3],
                             bl[nt][0], bl[nt][1]);
                    MMA16816(acc[mt][nt], al[mt][0], al[mt][1], al[mt][2], al[mt][3],
                             bh[nt][0], bh[nt][1]);
                }
        }
        // NOTE: no trailing __syncthreads — next iteration's top barrier
        // provides the producer/consumer ordering for stage reuse.
    }

    // epilogue (optionally fused RoPE for Q/K — validated in R7)
#pragma unroll
    for (int mt = 0; mt < 4; mt++) {
        const int row = bm + warp_m * 64 + mt * 16 + (lane >> 2);
#pragma unroll
        for (int nt = 0; nt < 4; nt++) {
            const int col = bn + warp_n * 32 + nt * 8 + (lane & 3) * 2;
            float v0 = acc[mt][nt][0], v1 = acc[mt][nt][1];
            float v2 = acc[mt][nt][2], v3 = acc[mt][nt][3];
            if (MODE == 1) {
                const int i = (col & (HD - 1)) >> 1;
                const int s1 = row & (SEQ - 1);
                const int s2 = (row + 8) & (SEQ - 1);
                const float c1 = __ldg(&fc[s1 * 64 + i]), n1 = __ldg(&fs[s1 * 64 + i]);
                const float c2 = __ldg(&fc[s2 * 64 + i]), n2 = __ldg(&fs[s2 * 64 + i]);
                float t;
                t  = v0 * c1 - v1 * n1; v1 = v0 * n1 + v1 * c1; v0 = t;
                t  = v2 * c2 - v3 * n2; v3 = v2 * n2 + v3 * c2; v2 = t;
            }
            *(float2*)&C[(size_t)row * D + col]       = make_float2(v0, v1);
            *(float2*)&C[(size_t)(row + 8) * D + col] = make_float2(v2, v3);
        }
    }
}

// ---------------- flash attention (fp32, causal) ---------------------------
// epilogue writes bf16 hi/lo directly (feeds O-projection GEMM).
#define ATTN_SMEM ((128 * 132 + 64 * 132 + 64 * 132 + 128 * 68) * 4)

__global__ void __launch_bounds__(256) attn_kernel() {
    extern __shared__ float smf[];
    float* Qs = smf;
    float* Ks = smf + 128 * 132;
    float* Vs = Ks + 64 * 132;
    float* Ps = Vs + 64 * 132;

    const int b = blockIdx.z, h = blockIdx.y, qt = blockIdx.x;
    const int q0 = qt * 128;
    const int tid = threadIdx.x;
    const int tx = tid & 7, ty = tid >> 3;
    const float SCALE = 0.08838834764831845f;

    const float* Qg = g_Q + ((size_t)(b * SEQ + q0)) * D + h * HD;
    const float* Kg = g_K + ((size_t)(b * SEQ)) * D + h * HD;
    const float* Vg = g_V + ((size_t)(b * SEQ)) * D + h * HD;

    for (int l = tid; l < 128 * 32; l += 256) {
        int row = l >> 5, c4 = l & 31;
        *(float4*)&Qs[row * 132 + c4 * 4] = *(const float4*)&Qg[(size_t)row * D + c4 * 4];
    }

    float o[4][16];
    float m[4], lsum[4];
#pragma unroll
    for (int r = 0; r < 4; r++) {
        m[r] = -1e30f; lsum[r] = 0.0f;
#pragma unroll
        for (int c = 0; c < 16; c++) o[r][c] = 0.0f;
    }

    const int ktiles = 2 * qt + 2;
    for (int kt = 0; kt < ktiles; kt++) {
        const int k0 = kt * 64;
        __syncthreads();
        for (int l = tid; l < 64 * 32; l += 256) {
            int row = l >> 5, c4 = l & 31;
            *(float4*)&Ks[row * 132 + c4 * 4] = *(const float4*)&Kg[(size_t)(k0 + row) * D + c4 * 4];
            *(float4*)&Vs[row * 132 + c4 * 4] = *(const float4*)&Vg[(size_t)(k0 + row) * D + c4 * 4];
        }
        __syncthreads();

        float sc[4][8];
#pragma unroll
        for (int r = 0; r < 4; r++)
#pragma unroll
            for (int c = 0; c < 8; c++) sc[r][c] = 0.0f;

#pragma unroll 4
        for (int kk4 = 0; kk4 < 32; kk4++) {
            float4 a4[4], b4[8];
#pragma unroll
            for (int r = 0; r < 4; r++)
                a4[r] = *(const float4*)&Qs[(ty * 4 + r) * 132 + kk4 * 4];
#pragma unroll
            for (int c = 0; c < 8; c++)
                b4[c] = *(const float4*)&Ks[(tx + 8 * c) * 132 + kk4 * 4];
#pragma unroll
            for (int r = 0; r < 4; r++)
#pragma unroll
                for (int c = 0; c < 8; c++)
                    sc[r][c] += a4[r].x * b4[c].x + a4[r].y * b4[c].y +
                                a4[r].z * b4[c].z + a4[r].w * b4[c].w;
        }

        const bool need_mask = (k0 + 63 > q0);
#pragma unroll
        for (int r = 0; r < 4; r++) {
            int ig = q0 + ty * 4 + r;
#pragma unroll
            for (int c = 0; c < 8; c++) {
                float v = sc[r][c] * SCALE;
                if (need_mask && (k0 + tx + 8 * c > ig)) v = -1e30f;
                sc[r][c] = v;
            }
        }

#pragma unroll
        for (int r = 0; r < 4; r++) {
            float mx = sc[r][0];
#pragma unroll
            for (int c = 1; c < 8; c++) mx = fmaxf(mx, sc[r][c]);
            mx = fmaxf(mx, __shfl_xor_sync(0xffffffffu, mx, 1));
            mx = fmaxf(mx, __shfl_xor_sync(0xffffffffu, mx, 2));
            mx = fmaxf(mx, __shfl_xor_sync(0xffffffffu, mx, 4));
            float mnew = fmaxf(m[r], mx);
            float alpha = __expf(m[r] - mnew);
            float s = 0.0f;
#pragma unroll
            for (int c = 0; c < 8; c++) {
                float p = __expf(sc[r][c] - mnew);
                sc[r][c] = p;
                s += p;
            }
            s += __shfl_xor_sync(0xffffffffu, s, 1);
            s += __shfl_xor_sync(0xffffffffu, s, 2);
            s += __shfl_xor_sync(0xffffffffu, s, 4);
            lsum[r] = lsum[r] * alpha + s;
            m[r] = mnew;
#pragma unroll
            for (int c = 0; c < 16; c++) o[r][c] *= alpha;
        }

#pragma unroll
        for (int r = 0; r < 4; r++)
#pragma unroll
            for (int c = 0; c < 8; c++)
                Ps[(ty * 4 + r) * 68 + tx + 8 * c] = sc[r][c];
        __syncthreads();

#pragma unroll 2
        for (int j = 0; j < 64; j++) {
            float p[4];
#pragma unroll
            for (int r = 0; r < 4; r++) p[r] = Ps[(ty * 4 + r) * 68 + j];
#pragma unroll
            for (int c = 0; c < 16; c++) {
                float v = Vs[j * 132 + tx + 8 * c];
#pragma unroll
                for (int r = 0; r < 4; r++) o[r][c] += p[r] * v;
            }
        }
    }

    // epilogue: normalize + split to bf16 hi/lo directly
#pragma unroll
    for (int r = 0; r < 4; r++) {
        float inv = 1.0f / lsum[r];
        size_t rowoff = ((size_t)(b * SEQ + q0 + ty * 4 + r)) * D + h * HD;
#pragma unroll
        for (int c = 0; c < 16; c++) {
            float val = o[r][c] * inv;
            __nv_bfloat16 hh = __float2bfloat16(val);
            g_Oh[rowoff + tx + 8 * c] = hh;
            g_Ol[rowoff + tx + 8 * c] = __float2bfloat16(val - __bfloat162float(hh));
        }
    }
}

// ---------------- launcher -------------------------------------------------
extern "C" void kernel_launch(void* const* d_in, const int* in_sizes, int n_in,
                              void* d_out, int out_size) {
    const float* x    = (const float*)d_in[0];
    const float* wq_w = (const float*)d_in[1];
    const float* wq_a = (const float*)d_in[2];
    const float* wq_b = (const float*)d_in[3];
    const float* wk_w = (const float*)d_in[4];
    const float* wv_w = (const float*)d_in[5];
    const float* wv_a = (const float*)d_in[6];
    const float* wv_b = (const float*)d_in[7];
    const float* wo_w = (const float*)d_in[8];
    const float* fc   = (const float*)d_in[9];
    const float* fs   = (const float*)d_in[10];
    float* out = (float*)d_out;

    __nv_bfloat16 *xh, *xl, *Wqh, *Wql, *Wkh, *Wkl, *Wvh, *Wvl, *Woh, *Wol, *Oh, *Ol;
    float *Q, *K, *V;
    cudaGetSymbolAddress((void**)&xh, g_xh);   cudaGetSymbolAddress((void**)&xl, g_xl);
    cudaGetSymbolAddress((void**)&Wqh, g_Wqh); cudaGetSymbolAddress((void**)&Wql, g_Wql);
    cudaGetSymbolAddress((void**)&Wkh, g_Wkh); cudaGetSymbolAddress((void**)&Wkl, g_Wkl);
    cudaGetSymbolAddress((void**)&Wvh, g_Wvh); cudaGetSymbolAddress((void**)&Wvl, g_Wvl);
    cudaGetSymbolAddress((void**)&Woh, g_Woh); cudaGetSymbolAddress((void**)&Wol, g_Wol);
    cudaGetSymbolAddress((void**)&Oh, g_Oh);   cudaGetSymbolAddress((void**)&Ol, g_Ol);
    cudaGetSymbolAddress((void**)&Q, g_Q);     cudaGetSymbolAddress((void**)&K, g_K);
    cudaGetSymbolAddress((void**)&V, g_V);

    cudaFuncSetAttribute(gemm_mma3<0>,
                         cudaFuncAttributeMaxDynamicSharedMemorySize, GEMM_SMEM);
    cudaFuncSetAttribute(gemm_mma3<1>,
                         cudaFuncAttributeMaxDynamicSharedMemorySize, GEMM_SMEM);
    cudaFuncSetAttribute(attn_kernel,
                         cudaFuncAttributeMaxDynamicSharedMemorySize, ATTN_SMEM);

    // 1) fold LoRA + split to bf16 hi/lo
    merge_split<<<(D * D) / 256, 256>>>(wq_w, wq_a, wq_b, Wqh, Wql);
    merge_split<<<(D * D) / 256, 256>>>(wv_w, wv_a, wv_b, Wvh, Wvl);
    split8<<<(D * D) / 8 / 256, 256>>>(wk_w, Wkh, Wkl);
    split8<<<(D * D) / 8 / 256, 256>>>(wo_w, Woh, Wol);
    split8<<<((size_t)BSR * D) / 8 / 256, 256>>>(x, xh, xl);

    // 2) projections on tensor cores; RoPE fused into Q/K epilogues
    dim3 g(D / 128, BSR / 128);  // (32, 32)
    gemm_mma3<1><<<g, 256, GEMM_SMEM>>>(xh, xl, Wqh, Wql, Q, fc, fs);
    gemm_mma3<1><<<g, 256, GEMM_SMEM>>>(xh, xl, Wkh, Wkl, K, fc, fs);
    gemm_mma3<0><<<g, 256, GEMM_SMEM>>>(xh, xl, Wvh, Wvl, V, fc, fs);

    // 3) causal flash attention -> g_Oh/g_Ol (bf16 split fused in epilogue)
    attn_kernel<<<dim3(SEQ / 128, NH, 4), 256, ATTN_SMEM>>>();

    // 4) output projection
    gemm_mma3<0><<<g, 256, GEMM_SMEM>>>(Oh, Ol, Woh, Wol, out, fc, fs);
}

// round 9
// speedup vs baseline: 1.9624x; 1.2008x over previous
#include <cuda_runtime.h>
#include <cuda_bf16.h>
#include <cstdint>

#define D   4096
#define BSR 4096
#define SEQ 1024
#define NH  32
#define HD  128
#define LR  16
#define SCALE 0.08838834764831845f

// ------------------------- device scratch ---------------------------------
__device__ __nv_bfloat16 g_xh[(size_t)BSR * D], g_xl[(size_t)BSR * D];
__device__ __nv_bfloat16 g_Wqh[(size_t)D * D], g_Wql[(size_t)D * D];
__device__ __nv_bfloat16 g_Wkh[(size_t)D * D], g_Wkl[(size_t)D * D];
__device__ __nv_bfloat16 g_Wvh[(size_t)D * D], g_Wvl[(size_t)D * D];
__device__ __nv_bfloat16 g_Woh[(size_t)D * D], g_Wol[(size_t)D * D];
__device__ __nv_bfloat16 g_Qh[(size_t)BSR * D], g_Ql[(size_t)BSR * D];
__device__ __nv_bfloat16 g_Kh[(size_t)BSR * D], g_Kl[(size_t)BSR * D];
__device__ __nv_bfloat16 g_Vh[(size_t)BSR * D], g_Vl[(size_t)BSR * D];
__device__ __nv_bfloat16 g_Oh[(size_t)BSR * D], g_Ol[(size_t)BSR * D];

// ------------------------- PTX helpers (base-target only) ------------------
__device__ __forceinline__ uint32_t smem_to_u32(const void* p) {
    uint32_t a;
    asm("{ .reg .u64 t; cvta.to.shared.u64 t, %1; cvt.u32.u64 %0, t; }"
        : "=r"(a) : "l"(p));
    return a;
}
#define CP16(dst, src) \
    asm volatile("cp.async.cg.shared.global [%0], [%1], 16;" \
                 :: "r"(dst), "l"(src))
#define CP_COMMIT() asm volatile("cp.async.commit_group;" ::: "memory")
#define CP_WAIT1()  asm volatile("cp.async.wait_group 1;" ::: "memory")
#define CP_WAIT0()  asm volatile("cp.async.wait_group 0;" ::: "memory")

#define LDSM4(r0, r1, r2, r3, addr) \
    asm volatile("ldmatrix.sync.aligned.m8n8.x4.shared.b16 {%0,%1,%2,%3}, [%4];" \
                 : "=r"(r0), "=r"(r1), "=r"(r2), "=r"(r3) : "r"(addr))
#define LDSM4T(r0, r1, r2, r3, addr) \
    asm volatile("ldmatrix.sync.aligned.m8n8.x4.trans.shared.b16 {%0,%1,%2,%3}, [%4];" \
                 : "=r"(r0), "=r"(r1), "=r"(r2), "=r"(r3) : "r"(addr))
#define LDSM2(r0, r1, addr) \
    asm volatile("ldmatrix.sync.aligned.m8n8.x2.shared.b16 {%0,%1}, [%2];" \
                 : "=r"(r0), "=r"(r1) : "r"(addr))
#define MMA16816(c, a0, a1, a2, a3, b0, b1) \
    asm volatile("mma.sync.aligned.m16n8k16.row.col.f32.bf16.bf16.f32 " \
                 "{%0,%1,%2,%3}, {%4,%5,%6,%7}, {%8,%9}, {%0,%1,%2,%3};" \
                 : "+f"((c)[0]), "+f"((c)[1]), "+f"((c)[2]), "+f"((c)[3]) \
                 : "r"(a0), "r"(a1), "r"(a2), "r"(a3), "r"(b0), "r"(b1))

// ------------------------- split / merge kernels --------------------------
__global__ void split8(const float* __restrict__ in,
                       __nv_bfloat16* __restrict__ hi,
                       __nv_bfloat16* __restrict__ lo) {
    size_t i = ((size_t)blockIdx.x * 256 + threadIdx.x) * 8;
    float v[8];
    *(float4*)&v[0] = *(const float4*)(in + i);
    *(float4*)&v[4] = *(const float4*)(in + i + 4);
    __nv_bfloat16 h[8], l[8];
#pragma unroll
    for (int j = 0; j < 8; j++) {
        h[j] = __float2bfloat16(v[j]);
        l[j] = __float2bfloat16(v[j] - __bfloat162float(h[j]));
    }
    *(float4*)(hi + i) = *(float4*)h;
    *(float4*)(lo + i) = *(float4*)l;
}

__global__ void merge_split(const float* __restrict__ w,
                            const float* __restrict__ a,
                            const float* __restrict__ b,
                            __nv_bfloat16* __restrict__ hi,
                            __nv_bfloat16* __restrict__ lo) {
    int idx = blockIdx.x * 256 + threadIdx.x;
    int n = idx >> 12, k = idx & (D - 1);
    float acc = w[idx];
#pragma unroll
    for (int r = 0; r < LR; r++)
        acc += 2.0f * __ldg(&b[n * LR + r]) * __ldg(&a[r * D + k]);
    __nv_bfloat16 h = __float2bfloat16(acc);
    hi[idx] = h;
    lo[idx] = __float2bfloat16(acc - __bfloat162float(h));
}

// ------------- bf16-split GEMM (NT) on mma.sync tensor cores --------------
// C = Ah*Bh^T + Ah*Bl^T + Al*Bh^T.  BM=BN=128, BK=64, 256 thr (8 warps 2x4).
// 3-stage cp.async pipeline, single barrier per chunk, tail-drained (R8 base).
// MODE: 0 = fp32 store (final out), 1 = bf16 hi/lo split store (V),
//       2 = RoPE + split (K),       3 = RoPE + scale + split (Q).
#define GTILE   16384
#define GSTAGE  (4 * GTILE)
#define NSTAGE  3
#define GEMM_SMEM (NSTAGE * GSTAGE)
#define NCHUNK  64   // D / BK

template <int MODE>
__global__ void __launch_bounds__(256, 1) gemm_mma3(
    const __nv_bfloat16* __restrict__ Ah, const __nv_bfloat16* __restrict__ Al,
    const __nv_bfloat16* __restrict__ Bh, const __nv_bfloat16* __restrict__ Bl,
    float* __restrict__ C,
    __nv_bfloat16* __restrict__ Ch, __nv_bfloat16* __restrict__ Cl,
    const float* __restrict__ fc, const float* __restrict__ fs) {
    extern __shared__ char smch[];
    const uint32_t smb = smem_to_u32(smch);
    const int tid = threadIdx.x, lane = tid & 31, wid = tid >> 5;
    const int warp_m = wid & 1;
    const int warp_n = wid >> 1;
    const int bm = blockIdx.y * 128, bn = blockIdx.x * 128;

    float acc[4][4][4];
#pragma unroll
    for (int i = 0; i < 4; i++)
#pragma unroll
        for (int j = 0; j < 4; j++)
#pragma unroll
            for (int k = 0; k < 4; k++) acc[i][j][k] = 0.0f;

    const int r0 = tid >> 3, c0 = tid & 7;
    const uint32_t dst0 = r0 * 128 + (uint32_t)((c0 ^ (r0 & 7)) * 16);
    const __nv_bfloat16* gAh = Ah + ((size_t)(bm + r0) << 12) + c0 * 8;
    const __nv_bfloat16* gAl = Al + ((size_t)(bm + r0) << 12) + c0 * 8;
    const __nv_bfloat16* gBh = Bh + ((size_t)(bn + r0) << 12) + c0 * 8;
    const __nv_bfloat16* gBl = Bl + ((size_t)(bn + r0) << 12) + c0 * 8;

#define ISSUE(ck, st) do {                                                     \
        const uint32_t sb_ = smb + (st) * GSTAGE + dst0;                       \
        const size_t go_ = (size_t)(ck) * 64;                                  \
        _Pragma("unroll")                                                      \
        for (int j = 0; j < 4; j++) {                                          \
            const uint32_t d_ = sb_ + j * 32 * 128;                            \
            const size_t s_ = go_ + ((size_t)j << 17);                         \
            CP16(d_,             (const char*)(gAh + s_));                     \
            CP16(d_ + GTILE,     (const char*)(gAl + s_));                     \
            CP16(d_ + 2 * GTILE, (const char*)(gBh + s_));                     \
            CP16(d_ + 3 * GTILE, (const char*)(gBl + s_));                     \
        }                                                                      \
        CP_COMMIT();                                                           \
    } while (0)

    ISSUE(0, 0);
    ISSUE(1, 1);

    const int arow = warp_m * 64 + (lane & 15);
    const int akh  = lane >> 4;
    const int brow = warp_n * 32 + (lane & 7);
    const int bkh  = (lane >> 3) & 1;

    for (int ck = 0; ck < NCHUNK; ck++) {
        const int st = ck % NSTAGE;
        if (ck + 2 >= NCHUNK) { CP_WAIT0(); } else { CP_WAIT1(); }
        __syncthreads();
        if (ck + 2 < NCHUNK) ISSUE(ck + 2, (ck + 2) % NSTAGE);

        const uint32_t sAh = smb + st * GSTAGE;
        const uint32_t sAl = sAh + GTILE;
        const uint32_t sBh = sAh + 2 * GTILE;
        const uint32_t sBl = sAh + 3 * GTILE;

#pragma unroll
        for (int ks = 0; ks < 4; ks++) {
            uint32_t ah[4][4], al[4][4], bh[4][2], bl[4][2];
#pragma unroll
            for (int mt = 0; mt < 4; mt++) {
                const int r = arow + mt * 16;
                const uint32_t adr = r * 128 + (((ks * 2 + akh) ^ (r & 7)) * 16);
                LDSM4(ah[mt][0], ah[mt][1], ah[mt][2], ah[mt][3], sAh + adr);
                LDSM4(al[mt][0], al[mt][1], al[mt][2], al[mt][3], sAl + adr);
            }
#pragma unroll
            for (int nt = 0; nt < 4; nt++) {
                const int r = brow + nt * 8;
                const uint32_t adr = r * 128 + (((ks * 2 + bkh) ^ (r & 7)) * 16);
                LDSM2(bh[nt][0], bh[nt][1], sBh + adr);
                LDSM2(bl[nt][0], bl[nt][1], sBl + adr);
            }
#pragma unroll
            for (int mt = 0; mt < 4; mt++)
#pragma unroll
                for (int nt = 0; nt < 4; nt++) {
                    MMA16816(acc[mt][nt], ah[mt][0], ah[mt][1], ah[mt][2], ah[mt][3],
                             bh[nt][0], bh[nt][1]);
                    MMA16816(acc[mt][nt], ah[mt][0], ah[mt][1], ah[mt][2], ah[mt][3],
                             bl[nt][0], bl[nt][1]);
                    MMA16816(acc[mt][nt], al[mt][0], al[mt][1], al[mt][2], al[mt][3],
                             bh[nt][0], bh[nt][1]);
                }
        }
    }

    // epilogue
#pragma unroll
    for (int mt = 0; mt < 4; mt++) {
        const int row = bm + warp_m * 64 + mt * 16 + (lane >> 2);
#pragma unroll
        for (int nt = 0; nt < 4; nt++) {
            const int col = bn + warp_n * 32 + nt * 8 + (lane & 3) * 2;
            float v0 = acc[mt][nt][0], v1 = acc[mt][nt][1];
            float v2 = acc[mt][nt][2], v3 = acc[mt][nt][3];
            if (MODE >= 2) {
                const int i = (col & (HD - 1)) >> 1;
                const int s1 = row & (SEQ - 1);
                const int s2 = (row + 8) & (SEQ - 1);
                const float c1 = __ldg(&fc[s1 * 64 + i]), n1 = __ldg(&fs[s1 * 64 + i]);
                const float c2 = __ldg(&fc[s2 * 64 + i]), n2 = __ldg(&fs[s2 * 64 + i]);
                float t;
                t  = v0 * c1 - v1 * n1; v1 = v0 * n1 + v1 * c1; v0 = t;
                t  = v2 * c2 - v3 * n2; v3 = v2 * n2 + v3 * c2; v2 = t;
            }
            if (MODE == 3) { v0 *= SCALE; v1 *= SCALE; v2 *= SCALE; v3 *= SCALE; }
            if (MODE == 0) {
                *(float2*)&C[(size_t)row * D + col]       = make_float2(v0, v1);
                *(float2*)&C[(size_t)(row + 8) * D + col] = make_float2(v2, v3);
            } else {
                __nv_bfloat16 h0 = __float2bfloat16(v0), h1 = __float2bfloat16(v1);
                __nv_bfloat162 hp; hp.x = h0; hp.y = h1;
                *(__nv_bfloat162*)&Ch[(size_t)row * D + col] = hp;
                __nv_bfloat162 lp;
                lp.x = __float2bfloat16(v0 - __bfloat162float(h0));
                lp.y = __float2bfloat16(v1 - __bfloat162float(h1));
                *(__nv_bfloat162*)&Cl[(size_t)row * D + col] = lp;
                __nv_bfloat16 h2 = __float2bfloat16(v2), h3 = __float2bfloat16(v3);
                __nv_bfloat162 hq; hq.x = h2; hq.y = h3;
                *(__nv_bfloat162*)&Ch[(size_t)(row + 8) * D + col] = hq;
                __nv_bfloat162 lq;
                lq.x = __float2bfloat16(v2 - __bfloat162float(h2));
                lq.y = __float2bfloat16(v3 - __bfloat162float(h3));
                *(__nv_bfloat162*)&Cl[(size_t)(row + 8) * D + col] = lq;
            }
        }
    }
}

// ---------------- MMA flash attention (bf16 hi/lo 3-term, causal) ----------
// Grid (8, NH, B). 256 thr = 8 warps; warp w owns q rows [w*16, w*16+16).
// Q tile 128x128 (hi/lo, 32KB each, loaded once); K/V tiles 64x128 hi/lo,
// double-buffered. Logical (row, d) -> smem row 2*row + d/64, 128B rows,
// XOR-swizzled 16B chunks. S = (Q*SCALE)K^T via mma; FA2 register softmax;
// P fragments built in-register from S fragments; PV via ldmatrix.trans.
#define AT_Q    0
#define AT_QL   32768
#define AT_ST   65536
#define AT_STSZ 65536   // Kh | Kl | Vh | Vl (16KB each)
#define ATTN_SMEM (AT_ST + 2 * AT_STSZ)

__global__ void __launch_bounds__(256, 1) attn_mma() {
    extern __shared__ char smc[];
    const uint32_t smb = smem_to_u32(smc);
    const int b = blockIdx.z, h = blockIdx.y, qt = blockIdx.x;
    const int q0 = qt * 128;
    const int tid = threadIdx.x, lane = tid & 31, wid = tid >> 5;

    const size_t qoff = ((size_t)(b * SEQ + q0) << 12) + (size_t)h * HD;
    const size_t koff = ((size_t)(b * SEQ) << 12) + (size_t)h * HD;

    // ---- Q hi/lo load (once): 2048 16B-chunks per tile, 8/thread ----
#pragma unroll
    for (int j = 0; j < 8; j++) {
        int q = tid + 256 * j;
        int r = q >> 4, dt = q & 15;
        int srow = 2 * r + (dt >> 3);
        uint32_t adr = srow * 128 + (uint32_t)((((dt & 7)) ^ (srow & 7)) * 16);
        const size_t go = qoff + ((size_t)r << 12) + dt * 8;
        CP16(smb + AT_Q  + adr, (const char*)(g_Qh + go));
        CP16(smb + AT_QL + adr, (const char*)(g_Ql + go));
    }

#define ISSUE_KV(kt, st) do {                                                  \
        const size_t kb_ = koff + ((size_t)((kt) * 64) << 12);                 \
        const uint32_t sb_ = smb + AT_ST + (st) * AT_STSZ;                     \
        _Pragma("unroll")                                                      \
        for (int j = 0; j < 4; j++) {                                          \
            int q_ = tid + 256 * j;                                            \
            int r_ = q_ >> 4, dt_ = q_ & 15;                                   \
            int sr_ = 2 * r_ + (dt_ >> 3);                                     \
            uint32_t ad_ = sr_ * 128 + (uint32_t)(((dt_ & 7) ^ (sr_ & 7)) * 16); \
            const size_t g_ = kb_ + ((size_t)r_ << 12) + dt_ * 8;              \
            CP16(sb_ + ad_,         (const char*)(g_Kh + g_));                 \
            CP16(sb_ + 16384 + ad_, (const char*)(g_Kl + g_));                 \
            CP16(sb_ + 32768 + ad_, (const char*)(g_Vh + g_));                 \
            CP16(sb_ + 49152 + ad_, (const char*)(g_Vl + g_));                 \
        }                                                                      \
        CP_COMMIT();                                                           \
    } while (0)

    ISSUE_KV(0, 0);   // commits Q loads too (same group)

    float o[16][4];
#pragma unroll
    for (int i = 0; i < 16; i++)
#pragma unroll
        for (int j = 0; j < 4; j++) o[i][j] = 0.0f;
    float m[2] = {-1e30f, -1e30f}, lsum[2] = {0.0f, 0.0f};

    const int ktiles = 2 * qt + 2;
    const int ar = wid * 16 + (lane & 15);     // q row (A frag)
    const int akh = lane >> 4;

    for (int kt = 0; kt < ktiles; kt++) {
        const int st = kt & 1;
        if (kt + 1 < ktiles) { ISSUE_KV(kt + 1, st ^ 1); CP_WAIT1(); }
        else                 { CP_WAIT0(); }
        __syncthreads();

        const uint32_t sQh = smb + AT_Q, sQl = smb + AT_QL;
        const uint32_t sKh = smb + AT_ST + st * AT_STSZ;
        const uint32_t sKl = sKh + 16384, sVh = sKh + 32768, sVl = sKh + 49152;

        // ---- S = Q K^T (3-term) ----
        float sc[8][4];
#pragma unroll
        for (int t = 0; t < 8; t++)
#pragma unroll
            for (int j = 0; j < 4; j++) sc[t][j] = 0.0f;

#pragma unroll
        for (int ks = 0; ks < 8; ks++) {
            const int qs = 2 * ar + (ks >> 2);
            const uint32_t aadr = qs * 128 +
                (uint32_t)(((((ks & 3) * 2 + akh)) ^ (qs & 7)) * 16);
            uint32_t qh[4], ql[4];
            LDSM4(qh[0], qh[1], qh[2], qh[3], sQh + aadr);
            LDSM4(ql[0], ql[1], ql[2], ql[3], sQl + aadr);
#pragma unroll
            for (int ntp = 0; ntp < 4; ntp++) {
                const int kr = ((lane >> 4) ? (2 * ntp + 1) : (2 * ntp)) * 8 + (lane & 7);
                const int kkh = (lane >> 3) & 1;
                const int ksr = 2 * kr + (ks >> 2);
                const uint32_t kadr = ksr * 128 +
                    (uint32_t)(((((ks & 3) * 2 + kkh)) ^ (ksr & 7)) * 16);
                uint32_t kh4[4], kl4[4];
                LDSM4(kh4[0], kh4[1], kh4[2], kh4[3], sKh + kadr);
                LDSM4(kl4[0], kl4[1], kl4[2], kl4[3], sKl + kadr);
                MMA16816(sc[2*ntp],   qh[0], qh[1], qh[2], qh[3], kh4[0], kh4[1]);
                MMA16816(sc[2*ntp],   qh[0], qh[1], qh[2], qh[3], kl4[0], kl4[1]);
                MMA16816(sc[2*ntp],   ql[0], ql[1], ql[2], ql[3], kh4[0], kh4[1]);
                MMA16816(sc[2*ntp+1], qh[0], qh[1], qh[2], qh[3], kh4[2], kh4[3]);
                MMA16816(sc[2*ntp+1], qh[0], qh[1], qh[2], qh[3], kl4[2], kl4[3]);
                MMA16816(sc[2*ntp+1], ql[0], ql[1], ql[2], ql[3], kh4[2], kh4[3]);
            }
        }

        // ---- causal mask ----
        const int k0 = kt * 64;
        if (k0 + 63 > q0) {
            const int rb = q0 + wid * 16 + (lane >> 2);
#pragma unroll
            for (int t = 0; t < 8; t++) {
                const int cb = k0 + t * 8 + (lane & 3) * 2;
                if (cb     > rb)     sc[t][0] = -1e30f;
                if (cb + 1 > rb)     sc[t][1] = -1e30f;
                if (cb     > rb + 8) sc[t][2] = -1e30f;
                if (cb + 1 > rb + 8) sc[t][3] = -1e30f;
            }
        }

        // ---- online softmax (per row half) ----
#pragma unroll
        for (int rh = 0; rh < 2; rh++) {
            float mx = -1e30f;
#pragma unroll
            for (int t = 0; t < 8; t++)
                mx = fmaxf(mx, fmaxf(sc[t][2*rh], sc[t][2*rh+1]));
            mx = fmaxf(mx, __shfl_xor_sync(0xffffffffu, mx, 1));
            mx = fmaxf(mx, __shfl_xor_sync(0xffffffffu, mx, 2));
            const float mnew = fmaxf(m[rh], mx);
            const float alpha = __expf(m[rh] - mnew);
            float s = 0.0f;
#pragma unroll
            for (int t = 0; t < 8; t++) {
                float p0 = __expf(sc[t][2*rh]   - mnew);
                float p1 = __expf(sc[t][2*rh+1] - mnew);
                sc[t][2*rh] = p0; sc[t][2*rh+1] = p1;
                s += p0 + p1;
            }
            s += __shfl_xor_sync(0xffffffffu, s, 1);
            s += __shfl_xor_sync(0xffffffffu, s, 2);
            lsum[rh] = lsum[rh] * alpha + s;
            m[rh] = mnew;
#pragma unroll
            for (int dt = 0; dt < 16; dt++) {
                o[dt][2*rh]   *= alpha;
                o[dt][2*rh+1] *= alpha;
            }
        }

        // ---- O += P V (3-term; P frags from registers, V via ldmatrix.trans)
#pragma unroll
        for (int kj = 0; kj < 4; kj++) {
            uint32_t ph[4], pl[4];
#pragma unroll
            for (int u = 0; u < 4; u++) {
                const float* sp = sc[2 * kj + (u >> 1)];
                const float v0 = sp[(u & 1) * 2], v1 = sp[(u & 1) * 2 + 1];
                __nv_bfloat16 h0 = __float2bfloat16(v0), h1 = __float2bfloat16(v1);
                __nv_bfloat162 hp; hp.x = h0; hp.y = h1;
                ph[u] = *(uint32_t*)&hp;
                __nv_bfloat162 lp;
                lp.x = __float2bfloat16(v0 - __bfloat162float(h0));
                lp.y = __float2bfloat16(v1 - __bfloat162float(h1));
                pl[u] = *(uint32_t*)&lp;
            }
            const int jr = kj * 16 + (lane & 7) + (((lane >> 3) & 1) << 3);
#pragma unroll
            for (int np = 0; np < 8; np++) {
                const int dtc = 2 * np + (lane >> 4);
                const int vsr = 2 * jr + (dtc >> 3);
                const uint32_t vadr = vsr * 128 +
                    (uint32_t)((((dtc & 7)) ^ (vsr & 7)) * 16);
                uint32_t vh4[4], vl4[4];
                LDSM4T(vh4[0], vh4[1], vh4[2], vh4[3], sVh + vadr);
                LDSM4T(vl4[0], vl4[1], vl4[2], vl4[3], sVl + vadr);
                MMA16816(o[2*np],   ph[0], ph[1], ph[2], ph[3], vh4[0], vh4[1]);
                MMA16816(o[2*np],   ph[0], ph[1], ph[2], ph[3], vl4[0], vl4[1]);
                MMA16816(o[2*np],   pl[0], pl[1], pl[2], pl[3], vh4[0], vh4[1]);
                MMA16816(o[2*np+1], ph[0], ph[1], ph[2], ph[3], vh4[2], vh4[3]);
                MMA16816(o[2*np+1], ph[0], ph[1], ph[2], ph[3], vl4[2], vl4[3]);
                MMA16816(o[2*np+1], pl[0], pl[1], pl[2], pl[3], vh4[2], vh4[3]);
            }
        }
        __syncthreads();
    }

    // ---- epilogue: normalize + bf16 hi/lo split ----
#pragma unroll
    for (int rh = 0; rh < 2; rh++) {
        const float inv = 1.0f / lsum[rh];
        const int row = q0 + wid * 16 + (lane >> 2) + rh * 8;
        const size_t ro = ((size_t)(b * SEQ + row) << 12) + (size_t)h * HD
                          + (lane & 3) * 2;
#pragma unroll
        for (int dt = 0; dt < 16; dt++) {
            const float v0 = o[dt][2*rh] * inv, v1 = o[dt][2*rh+1] * inv;
            __nv_bfloat16 h0 = __float2bfloat16(v0), h1 = __float2bfloat16(v1);
            __nv_bfloat162 hp; hp.x = h0; hp.y = h1;
            *(__nv_bfloat162*)&g_Oh[ro + dt * 8] = hp;
            __nv_bfloat162 lp;
            lp.x = __float2bfloat16(v0 - __bfloat162float(h0));
            lp.y = __float2bfloat16(v1 - __bfloat162float(h1));
            *(__nv_bfloat162*)&g_Ol[ro + dt * 8] = lp;
        }
    }
}

// ---------------- launcher -------------------------------------------------
extern "C" void kernel_launch(void* const* d_in, const int* in_sizes, int n_in,
                              void* d_out, int out_size) {
    const float* x    = (const float*)d_in[0];
    const float* wq_w = (const float*)d_in[1];
    const float* wq_a = (const float*)d_in[2];
    const float* wq_b = (const float*)d_in[3];
    const float* wk_w = (const float*)d_in[4];
    const float* wv_w = (const float*)d_in[5];
    const float* wv_a = (const float*)d_in[6];
    const float* wv_b = (const float*)d_in[7];
    const float* wo_w = (const float*)d_in[8];
    const float* fc   = (const float*)d_in[9];
    const float* fs   = (const float*)d_in[10];
    float* out = (float*)d_out;

    __nv_bfloat16 *xh, *xl, *Wqh, *Wql, *Wkh, *Wkl, *Wvh, *Wvl, *Woh, *Wol;
    __nv_bfloat16 *Qh, *Ql, *Kh, *Kl, *Vh, *Vl, *Oh, *Ol;
    cudaGetSymbolAddress((void**)&xh, g_xh);   cudaGetSymbolAddress((void**)&xl, g_xl);
    cudaGetSymbolAddress((void**)&Wqh, g_Wqh); cudaGetSymbolAddress((void**)&Wql, g_Wql);
    cudaGetSymbolAddress((void**)&Wkh, g_Wkh); cudaGetSymbolAddress((void**)&Wkl, g_Wkl);
    cudaGetSymbolAddress((void**)&Wvh, g_Wvh); cudaGetSymbolAddress((void**)&Wvl, g_Wvl);
    cudaGetSymbolAddress((void**)&Woh, g_Woh); cudaGetSymbolAddress((void**)&Wol, g_Wol);
    cudaGetSymbolAddress((void**)&Qh, g_Qh);   cudaGetSymbolAddress((void**)&Ql, g_Ql);
    cudaGetSymbolAddress((void**)&Kh, g_Kh);   cudaGetSymbolAddress((void**)&Kl, g_Kl);
    cudaGetSymbolAddress((void**)&Vh, g_Vh);   cudaGetSymbolAddress((void**)&Vl, g_Vl);
    cudaGetSymbolAddress((void**)&Oh, g_Oh);   cudaGetSymbolAddress((void**)&Ol, g_Ol);

    cudaFuncSetAttribute(gemm_mma3<0>, cudaFuncAttributeMaxDynamicSharedMemorySize, GEMM_SMEM);
    cudaFuncSetAttribute(gemm_mma3<1>, cudaFuncAttributeMaxDynamicSharedMemorySize, GEMM_SMEM);
    cudaFuncSetAttribute(gemm_mma3<2>, cudaFuncAttributeMaxDynamicSharedMemorySize, GEMM_SMEM);
    cudaFuncSetAttribute(gemm_mma3<3>, cudaFuncAttributeMaxDynamicSharedMemorySize, GEMM_SMEM);
    cudaFuncSetAttribute(attn_mma, cudaFuncAttributeMaxDynamicSharedMemorySize, ATTN_SMEM);

    // 1) fold LoRA + split to bf16 hi/lo
    merge_split<<<(D * D) / 256, 256>>>(wq_w, wq_a, wq_b, Wqh, Wql);
    merge_split<<<(D * D) / 256, 256>>>(wv_w, wv_a, wv_b, Wvh, Wvl);
    split8<<<(D * D) / 8 / 256, 256>>>(wk_w, Wkh, Wkl);
    split8<<<(D * D) / 8 / 256, 256>>>(wo_w, Woh, Wol);
    split8<<<((size_t)BSR * D) / 8 / 256, 256>>>(x, xh, xl);

    // 2) projections -> bf16 hi/lo; RoPE fused (K), RoPE+scale fused (Q)
    dim3 g(D / 128, BSR / 128);
    gemm_mma3<3><<<g, 256, GEMM_SMEM>>>(xh, xl, Wqh, Wql, nullptr, Qh, Ql, fc, fs);
    gemm_mma3<2><<<g, 256, GEMM_SMEM>>>(xh, xl, Wkh, Wkl, nullptr, Kh, Kl, fc, fs);
    gemm_mma3<1><<<g, 256, GEMM_SMEM>>>(xh, xl, Wvh, Wvl, nullptr, Vh, Vl, fc, fs);

    // 3) MMA flash attention -> g_Oh/g_Ol
    attn_mma<<<dim3(SEQ / 128, NH, 4), 256, ATTN_SMEM>>>();

    // 4) output projection (fp32 out)
    gemm_mma3<0><<<g, 256, GEMM_SMEM>>>(Oh, Ol, Woh, Wol, out, nullptr, nullptr, fc, fs);
}